// round 1
// baseline (speedup 1.0000x reference)
#include <cuda_runtime.h>
#include <math.h>

#define B_   32
#define KV_  4096
#define H_   4096
#define NH_  32
#define NKV_ 8
#define D_   128
#define G_   4
#define QKVN ((NH_ + 2*NKV_) * D_)   // 6144
#define SCALE_ 0.08838834764831845f  // 128^-0.5

// ---- scratch (device globals: no allocation) ----
__device__ float g_qkv[B_ * QKVN];                 // 786 KB
__device__ float g_scores[B_ * NKV_ * G_ * KV_];   // 16 MB
__device__ float g_o[B_ * NH_ * D_];               // 512 KB

// ============================================================
// GEMM: C[32, N] = A[32, K] * W[N, K]^T   (all row-major fp32)
// tile 32(M) x 64(N), k-chunk 32, 128 threads, 4x4 per thread
// ============================================================
__global__ void gemm32(const float* __restrict__ A, const float* __restrict__ W,
                       float* __restrict__ C, int N, int K) {
    __shared__ float As[32][36];   // As[kk][m], stride 36 keeps 16B align
    __shared__ float Ws[32][68];   // Ws[kk][n]
    const int tid = threadIdx.x;
    const int tx = tid & 15;       // n sub-tile 0..15
    const int ty = tid >> 4;       // m sub-tile 0..7
    const int n0 = blockIdx.x * 64;

    float acc[4][4];
    #pragma unroll
    for (int i = 0; i < 4; i++)
        #pragma unroll
        for (int j = 0; j < 4; j++) acc[i][j] = 0.f;

    for (int k0 = 0; k0 < K; k0 += 32) {
        // load A chunk: 32x32 = 256 float4, 2 per thread, store transposed
        #pragma unroll
        for (int j = 0; j < 2; j++) {
            int f = tid + j * 128;
            int m = f >> 3, c = (f & 7) * 4;
            float4 a = *(const float4*)&A[m * K + k0 + c];
            As[c + 0][m] = a.x; As[c + 1][m] = a.y;
            As[c + 2][m] = a.z; As[c + 3][m] = a.w;
        }
        // load W chunk: 64x32 = 512 float4, 4 per thread
        #pragma unroll
        for (int j = 0; j < 4; j++) {
            int f = tid + j * 128;
            int n = f >> 3, c = (f & 7) * 4;
            float4 w = *(const float4*)&W[(size_t)(n0 + n) * K + k0 + c];
            Ws[c + 0][n] = w.x; Ws[c + 1][n] = w.y;
            Ws[c + 2][n] = w.z; Ws[c + 3][n] = w.w;
        }
        __syncthreads();
        #pragma unroll
        for (int kk = 0; kk < 32; kk++) {
            float4 a4 = *(const float4*)&As[kk][ty * 4];
            float4 b4 = *(const float4*)&Ws[kk][tx * 4];
            float av[4] = {a4.x, a4.y, a4.z, a4.w};
            float bv[4] = {b4.x, b4.y, b4.z, b4.w};
            #pragma unroll
            for (int i = 0; i < 4; i++)
                #pragma unroll
                for (int j = 0; j < 4; j++) acc[i][j] += av[i] * bv[j];
        }
        __syncthreads();
    }
    #pragma unroll
    for (int i = 0; i < 4; i++)
        #pragma unroll
        for (int j = 0; j < 4; j++)
            C[(ty * 4 + i) * N + n0 + tx * 4 + j] = acc[i][j];
}

// ============================================================
// RMSNorm (q,k heads) + NeoX RoPE + scatter k,v into cache.
// grid (48 heads, 32 batch), 128 threads (one per d).
// heads 0..31=q (in-place in g_qkv), 32..39=k (-> k_buffer), 40..47=v (-> v_buffer)
// ============================================================
__global__ void norm_rope_scatter(const float* __restrict__ q_norm_w,
                                  const float* __restrict__ k_norm_w,
                                  const int* __restrict__ position_ids,
                                  const int* __restrict__ out_cache_loc,
                                  float* __restrict__ k_buf,
                                  float* __restrict__ v_buf) {
    const int head = blockIdx.x;
    const int b = blockIdx.y;
    const int tid = threadIdx.x;
    const float x = g_qkv[b * QKVN + head * D_ + tid];

    if (head >= NH_ + NKV_) {  // v head: raw scatter
        int h = head - (NH_ + NKV_);
        int loc = out_cache_loc[b];
        v_buf[(((size_t)b * KV_ + loc) * NKV_ + h) * D_ + tid] = x;
        return;
    }

    // --- RMSNorm ---
    __shared__ float sred[4];
    float ss = x * x;
    #pragma unroll
    for (int o = 16; o; o >>= 1) ss += __shfl_xor_sync(0xffffffffu, ss, o);
    if ((tid & 31) == 0) sred[tid >> 5] = ss;
    __syncthreads();
    float total = sred[0] + sred[1] + sred[2] + sred[3];
    float rms = rsqrtf(total * (1.0f / D_) + 1e-6f);
    const float* wn = (head < NH_) ? q_norm_w : k_norm_w;
    float y = x * rms * wn[tid];

    // --- RoPE (NeoX) ---
    __shared__ float ys[128];
    ys[tid] = y;
    __syncthreads();
    int i = tid & 63;
    double invf = pow(1.0e6, -(double)i / 64.0);
    double ang = (double)position_ids[b] * invf;
    float c = (float)cos(ang), s = (float)sin(ang);
    float out = (tid < 64) ? (ys[tid] * c - ys[tid + 64] * s)
                           : (ys[tid] * c + ys[tid - 64] * s);

    if (head < NH_) {
        g_qkv[b * QKVN + head * D_ + tid] = out;
    } else {
        int h = head - NH_;
        int loc = out_cache_loc[b];
        k_buf[(((size_t)b * KV_ + loc) * NKV_ + h) * D_ + tid] = out;
    }
}

// ============================================================
// QK scores: grid (chunk=8, h=8, b=32), 256 threads (8 warps).
// Warp handles one s at a time; 4 GQA heads share the K load.
// ============================================================
__global__ void scores_kernel(const float* __restrict__ k_buf) {
    const int chunk = blockIdx.x, h = blockIdx.y, b = blockIdx.z;
    const int tid = threadIdx.x;
    const int warp = tid >> 5, lane = tid & 31;
    __shared__ float sc[4][512];

    // q fragments (4 heads x 4 floats per lane)
    float4 q4[G_];
    #pragma unroll
    for (int g = 0; g < G_; g++)
        q4[g] = *(const float4*)&g_qkv[b * QKVN + (h * G_ + g) * D_ + lane * 4];

    const int s0 = chunk * 512;
    #pragma unroll 2
    for (int i = warp; i < 512; i += 8) {
        int s = s0 + i;
        float4 kv = *(const float4*)&k_buf[(((size_t)b * KV_ + s) * NKV_ + h) * D_ + lane * 4];
        float p[G_];
        #pragma unroll
        for (int g = 0; g < G_; g++)
            p[g] = q4[g].x * kv.x + q4[g].y * kv.y + q4[g].z * kv.z + q4[g].w * kv.w;
        #pragma unroll
        for (int g = 0; g < G_; g++)
            #pragma unroll
            for (int o = 16; o; o >>= 1) p[g] += __shfl_xor_sync(0xffffffffu, p[g], o);
        if (lane == 0) {
            #pragma unroll
            for (int g = 0; g < G_; g++) sc[g][i] = p[g] * SCALE_;
        }
    }
    __syncthreads();
    // coalesced write-out
    for (int idx = tid; idx < 4 * 512; idx += 256) {
        int g = idx >> 9, sl = idx & 511;
        g_scores[((b * NKV_ + h) * G_ + g) * KV_ + s0 + sl] = sc[g][sl];
    }
}

// ============================================================
// Softmax in place over g_scores rows (1024 rows of 4096)
// ============================================================
__global__ void softmax_kernel() {
    float* p = g_scores + (size_t)blockIdx.x * KV_;
    const int tid = threadIdx.x;
    __shared__ float sm[8];

    float m = -1e30f;
    for (int i = tid; i < KV_; i += 256) m = fmaxf(m, p[i]);
    #pragma unroll
    for (int o = 16; o; o >>= 1) m = fmaxf(m, __shfl_xor_sync(0xffffffffu, m, o));
    if ((tid & 31) == 0) sm[tid >> 5] = m;
    __syncthreads();
    if (tid < 32) {
        float v = (tid < 8) ? sm[tid] : -1e30f;
        #pragma unroll
        for (int o = 4; o; o >>= 1) v = fmaxf(v, __shfl_xor_sync(0xffffffffu, v, o));
        if (tid == 0) sm[0] = v;
    }
    __syncthreads();
    const float M = sm[0];
    __syncthreads();

    float sum = 0.f;
    for (int i = tid; i < KV_; i += 256) {
        float e = __expf(p[i] - M);
        p[i] = e;
        sum += e;
    }
    #pragma unroll
    for (int o = 16; o; o >>= 1) sum += __shfl_xor_sync(0xffffffffu, sum, o);
    if ((tid & 31) == 0) sm[tid >> 5] = sum;
    __syncthreads();
    if (tid < 32) {
        float v = (tid < 8) ? sm[tid] : 0.f;
        #pragma unroll
        for (int o = 4; o; o >>= 1) v += __shfl_xor_sync(0xffffffffu, v, o);
        if (tid == 0) sm[0] = v;
    }
    __syncthreads();
    const float inv = 1.0f / sm[0];
    for (int i = tid; i < KV_; i += 256) p[i] *= inv;
}

// ============================================================
// PV: o[b, h, g, d] = sum_s p[b,h,g,s] * v[b,s,h,d]
// grid (h=8, b=32), 128 threads (one per d), 4 accumulators per thread.
// ============================================================
__global__ void pv_kernel(const float* __restrict__ v_buf) {
    const int h = blockIdx.x, b = blockIdx.y;
    const int tid = threadIdx.x;
    __shared__ float psh[4][128];

    float acc[G_] = {0.f, 0.f, 0.f, 0.f};
    const size_t vbase = (((size_t)b * KV_) * NKV_ + h) * D_ + tid;
    const size_t pbase = ((size_t)(b * NKV_ + h) * G_) * KV_;

    for (int ch = 0; ch < KV_ / 128; ch++) {
        #pragma unroll
        for (int j = 0; j < 4; j++) {
            int idx = tid + j * 128;          // 512 values
            int g = idx >> 7, sl = idx & 127;
            psh[g][sl] = g_scores[pbase + (size_t)g * KV_ + ch * 128 + sl];
        }
        __syncthreads();
        #pragma unroll 4
        for (int sl = 0; sl < 128; sl++) {
            float v = v_buf[vbase + (size_t)(ch * 128 + sl) * NKV_ * D_];
            #pragma unroll
            for (int g = 0; g < G_; g++) acc[g] += psh[g][sl] * v;
        }
        __syncthreads();
    }
    #pragma unroll
    for (int g = 0; g < G_; g++)
        g_o[b * (NH_ * D_) + (h * G_ + g) * D_ + tid] = acc[g];
}

// ============================================================
extern "C" void kernel_launch(void* const* d_in, const int* in_sizes, int n_in,
                              void* d_out, int out_size) {
    const int*   position_ids  = (const int*)  d_in[0];
    const float* hidden_states = (const float*)d_in[1];
    float*       k_buffer      = (float*)      d_in[2];
    float*       v_buffer      = (float*)      d_in[3];
    const int*   out_cache_loc = (const int*)  d_in[4];
    const float* wqkv          = (const float*)d_in[5];
    const float* wo            = (const float*)d_in[6];
    const float* q_norm_w      = (const float*)d_in[7];
    const float* k_norm_w      = (const float*)d_in[8];
    float* out = (float*)d_out;

    float* qkv_ptr;    cudaGetSymbolAddress((void**)&qkv_ptr, g_qkv);
    float* o_ptr;      cudaGetSymbolAddress((void**)&o_ptr, g_o);

    // 1. QKV projection: [32,6144]
    gemm32<<<QKVN / 64, 128>>>(hidden_states, wqkv, qkv_ptr, QKVN, H_);
    // 2. per-head RMSNorm + RoPE + scatter into caches
    norm_rope_scatter<<<dim3(NH_ + 2 * NKV_, B_), 128>>>(
        q_norm_w, k_norm_w, position_ids, out_cache_loc, k_buffer, v_buffer);
    // 3. QK scores
    scores_kernel<<<dim3(KV_ / 512, NKV_, B_), 256>>>(k_buffer);
    // 4. softmax
    softmax_kernel<<<B_ * NKV_ * G_, 256>>>();
    // 5. PV
    pv_kernel<<<dim3(NKV_, B_), 128>>>(v_buffer);
    // 6. output projection: [32,4096]
    gemm32<<<H_ / 64, 128>>>(o_ptr, wo, out, H_, H_);
}

// round 2
// speedup vs baseline: 2.4706x; 2.4706x over previous
#include <cuda_runtime.h>
#include <math.h>

#define B_   32
#define KV_  4096
#define H_   4096
#define NH_  32
#define NKV_ 8
#define D_   128
#define G_   4
#define QKVN ((NH_ + 2*NKV_) * D_)   // 6144
#define SCALE_ 0.08838834764831845f  // 128^-0.5
#define SPLITK 8

// ---- scratch (device globals: no allocation) ----
__device__ float g_qkv[B_ * QKVN];                  // final q (roped) lives here
__device__ float g_part[SPLITK * B_ * QKVN];        // split-K partials (6.3 MB, reused)
__device__ float g_scores[B_ * NKV_ * G_ * KV_];    // 16 MB raw scores
__device__ float g_o[B_ * NH_ * D_];                // attention output

// ============================================================
// Split-K GEMM: P[s][32][N] = A[32, kslice] * W[N, kslice]^T
// tile 32(M) x 128(N), k-chunk 32, 256 threads, 4x4 per thread
// ============================================================
__global__ __launch_bounds__(256) void gemm_splitk(
        const float* __restrict__ A, const float* __restrict__ W,
        float* __restrict__ P, int N, int K) {
    __shared__ float As[32][36];
    __shared__ float Ws[32][132];
    const int tid = threadIdx.x;
    const int tx = tid & 31;      // n sub-tile
    const int ty = tid >> 5;      // m sub-tile
    const int n0 = blockIdx.x * 128;
    const int kslice = K / SPLITK;
    const int kbase = blockIdx.y * kslice;

    float acc[4][4];
    #pragma unroll
    for (int i = 0; i < 4; i++)
        #pragma unroll
        for (int j = 0; j < 4; j++) acc[i][j] = 0.f;

    for (int k0 = kbase; k0 < kbase + kslice; k0 += 32) {
        // A chunk 32x32 = 256 float4, 1 per thread (stored transposed)
        {
            int m = tid >> 3, c = (tid & 7) * 4;
            float4 a = *(const float4*)&A[m * K + k0 + c];
            As[c + 0][m] = a.x; As[c + 1][m] = a.y;
            As[c + 2][m] = a.z; As[c + 3][m] = a.w;
        }
        // W chunk 128x32 = 1024 float4, 4 per thread
        #pragma unroll
        for (int j = 0; j < 4; j++) {
            int f = tid + j * 256;
            int n = f >> 3, c = (f & 7) * 4;
            float4 w = *(const float4*)&W[(size_t)(n0 + n) * K + k0 + c];
            Ws[c + 0][n] = w.x; Ws[c + 1][n] = w.y;
            Ws[c + 2][n] = w.z; Ws[c + 3][n] = w.w;
        }
        __syncthreads();
        #pragma unroll
        for (int kk = 0; kk < 32; kk++) {
            float4 a4 = *(const float4*)&As[kk][ty * 4];   // broadcast within warp
            float4 b4 = *(const float4*)&Ws[kk][tx * 4];
            float av[4] = {a4.x, a4.y, a4.z, a4.w};
            float bv[4] = {b4.x, b4.y, b4.z, b4.w};
            #pragma unroll
            for (int i = 0; i < 4; i++)
                #pragma unroll
                for (int j = 0; j < 4; j++) acc[i][j] += av[i] * bv[j];
        }
        __syncthreads();
    }
    float* p = P + (size_t)blockIdx.y * 32 * N;
    #pragma unroll
    for (int i = 0; i < 4; i++)
        *(float4*)&p[(ty * 4 + i) * N + n0 + tx * 4] =
            make_float4(acc[i][0], acc[i][1], acc[i][2], acc[i][3]);
}

// reduce split-K partials for the O projection into d_out (float4)
__global__ void reduce_out(float* __restrict__ out, int total4) {
    int i = blockIdx.x * blockDim.x + threadIdx.x;
    if (i >= total4) return;
    float4 r = make_float4(0.f, 0.f, 0.f, 0.f);
    #pragma unroll
    for (int s = 0; s < SPLITK; s++) {
        float4 x = *(const float4*)&g_part[(size_t)s * (B_ * H_) + i * 4];
        r.x += x.x; r.y += x.y; r.z += x.z; r.w += x.w;
    }
    ((float4*)out)[i] = r;
}

// ============================================================
// split-K reduce (QKV) + RMSNorm + NeoX RoPE + scatter k,v.
// grid (48 heads, 32 batch), 128 threads (one per d).
// ============================================================
__global__ void norm_rope_scatter(const float* __restrict__ q_norm_w,
                                  const float* __restrict__ k_norm_w,
                                  const int* __restrict__ position_ids,
                                  const int* __restrict__ out_cache_loc,
                                  float* __restrict__ k_buf,
                                  float* __restrict__ v_buf) {
    const int head = blockIdx.x;
    const int b = blockIdx.y;
    const int tid = threadIdx.x;
    const int off = b * QKVN + head * D_ + tid;

    float x = 0.f;
    #pragma unroll
    for (int s = 0; s < SPLITK; s++) x += g_part[(size_t)s * (B_ * QKVN) + off];

    if (head >= NH_ + NKV_) {  // v head: raw scatter
        int h = head - (NH_ + NKV_);
        int loc = out_cache_loc[b];
        v_buf[(((size_t)b * KV_ + loc) * NKV_ + h) * D_ + tid] = x;
        return;
    }

    // --- RMSNorm ---
    __shared__ float sred[4];
    float ss = x * x;
    #pragma unroll
    for (int o = 16; o; o >>= 1) ss += __shfl_xor_sync(0xffffffffu, ss, o);
    if ((tid & 31) == 0) sred[tid >> 5] = ss;
    __syncthreads();
    float total = sred[0] + sred[1] + sred[2] + sred[3];
    float rms = rsqrtf(total * (1.0f / D_) + 1e-6f);
    const float* wn = (head < NH_) ? q_norm_w : k_norm_w;
    float y = x * rms * wn[tid];

    // --- RoPE (NeoX) ---
    __shared__ float ys[128];
    ys[tid] = y;
    __syncthreads();
    int i = tid & 63;
    double invf = pow(1.0e6, -(double)i / 64.0);
    double ang = (double)position_ids[b] * invf;
    float c = (float)cos(ang), s = (float)sin(ang);
    float outv = (tid < 64) ? (ys[tid] * c - ys[tid + 64] * s)
                            : (ys[tid] * c + ys[tid - 64] * s);

    if (head < NH_) {
        g_qkv[off] = outv;
    } else {
        int h = head - NH_;
        int loc = out_cache_loc[b];
        k_buf[(((size_t)b * KV_ + loc) * NKV_ + h) * D_ + tid] = outv;
    }
}

// ============================================================
// QK scores: grid (chunk=8, h=8, b=32), 256 threads (8 warps).
// ============================================================
__global__ void scores_kernel(const float* __restrict__ k_buf) {
    const int chunk = blockIdx.x, h = blockIdx.y, b = blockIdx.z;
    const int tid = threadIdx.x;
    const int warp = tid >> 5, lane = tid & 31;
    __shared__ float sc[4][512];

    float4 q4[G_];
    #pragma unroll
    for (int g = 0; g < G_; g++)
        q4[g] = *(const float4*)&g_qkv[b * QKVN + (h * G_ + g) * D_ + lane * 4];

    const int s0 = chunk * 512;
    #pragma unroll 2
    for (int i = warp; i < 512; i += 8) {
        int s = s0 + i;
        float4 kv = *(const float4*)&k_buf[(((size_t)b * KV_ + s) * NKV_ + h) * D_ + lane * 4];
        float p[G_];
        #pragma unroll
        for (int g = 0; g < G_; g++)
            p[g] = q4[g].x * kv.x + q4[g].y * kv.y + q4[g].z * kv.z + q4[g].w * kv.w;
        #pragma unroll
        for (int g = 0; g < G_; g++)
            #pragma unroll
            for (int o = 16; o; o >>= 1) p[g] += __shfl_xor_sync(0xffffffffu, p[g], o);
        if (lane == 0) {
            #pragma unroll
            for (int g = 0; g < G_; g++) sc[g][i] = p[g] * SCALE_;
        }
    }
    __syncthreads();
    for (int idx = tid; idx < 4 * 512; idx += 256) {
        int g = idx >> 9, sl = idx & 511;
        g_scores[((b * NKV_ + h) * G_ + g) * KV_ + s0 + sl] = sc[g][sl];
    }
}

// ============================================================
// Fused softmax + PV. grid (h=8, b=32), 512 threads.
// Phase A: each 128-thread s-group computes online (max,sum) of one g-row.
// Phase B: 4 s-groups each accumulate 1024 s-slots; exp applied at staging.
// ============================================================
__global__ __launch_bounds__(512) void softmax_pv_kernel(const float* __restrict__ v_buf) {
    const int h = blockIdx.x, b = blockIdx.y;
    const int tid = threadIdx.x;
    const int d = tid & 127;         // head-dim lane
    const int sg = tid >> 7;         // s-group 0..3 (also = g-row in phase A)
    const int warp = tid >> 5, lane = tid & 31;

    __shared__ float psh[4][4][128];   // [sg][g][sl] staged probabilities
    __shared__ float wms[16][2];       // per-warp (m,s) partials
    __shared__ float gms[4][2];        // per-g final (max, inv_sum)

    const size_t pbase = ((size_t)(b * NKV_ + h) * G_) * KV_;

    // ---- Phase A: online (m,s) for row g = sg ----
    {
        const float* row = g_scores + pbase + (size_t)sg * KV_;
        float m = -1e30f, s = 0.f;
        #pragma unroll
        for (int j = 0; j < 8; j++) {
            float4 x = *(const float4*)&row[(d + j * 128) * 4];
            float lm = fmaxf(fmaxf(x.x, x.y), fmaxf(x.z, x.w));
            float nm = fmaxf(m, lm);
            s = s * __expf(m - nm) + __expf(x.x - nm) + __expf(x.y - nm)
                                   + __expf(x.z - nm) + __expf(x.w - nm);
            m = nm;
        }
        #pragma unroll
        for (int o = 16; o; o >>= 1) {
            float om = __shfl_xor_sync(0xffffffffu, m, o);
            float os = __shfl_xor_sync(0xffffffffu, s, o);
            float nm = fmaxf(m, om);
            s = s * __expf(m - nm) + os * __expf(om - nm);
            m = nm;
        }
        if (lane == 0) { wms[warp][0] = m; wms[warp][1] = s; }
    }
    __syncthreads();
    if (tid < 4) {   // combine 4 warps of each g-row
        int g = tid;
        float m = -1e30f, s = 0.f;
        #pragma unroll
        for (int w = 0; w < 4; w++) {
            float om = wms[g * 4 + w][0], os = wms[g * 4 + w][1];
            float nm = fmaxf(m, om);
            s = s * __expf(m - nm) + os * __expf(om - nm);
            m = nm;
        }
        gms[g][0] = m; gms[g][1] = 1.0f / s;
    }
    __syncthreads();

    // ---- Phase B: PV accumulation, s-group sg handles s in [sg*1024, sg*1024+1024) ----
    float acc[G_] = {0.f, 0.f, 0.f, 0.f};
    const size_t vbase = ((size_t)b * KV_) * (NKV_ * D_) + h * D_ + d;

    for (int ch = 0; ch < 8; ch++) {
        const int s0 = sg * 1024 + ch * 128;
        #pragma unroll
        for (int g = 0; g < G_; g++) {
            float raw = g_scores[pbase + (size_t)g * KV_ + s0 + d];
            psh[sg][g][d] = __expf(raw - gms[g][0]) * gms[g][1];
        }
        __syncthreads();
        #pragma unroll 8
        for (int sl = 0; sl < 128; sl++) {
            float v = v_buf[vbase + (size_t)(s0 + sl) * (NKV_ * D_)];
            #pragma unroll
            for (int g = 0; g < G_; g++) acc[g] += psh[sg][g][sl] * v;
        }
        __syncthreads();
    }

    // ---- combine the 4 s-groups ----
    #pragma unroll
    for (int g = 0; g < G_; g++) psh[sg][g][d] = acc[g];
    __syncthreads();
    if (sg == 0) {
        #pragma unroll
        for (int g = 0; g < G_; g++) {
            float r = psh[0][g][d] + psh[1][g][d] + psh[2][g][d] + psh[3][g][d];
            g_o[b * (NH_ * D_) + (h * G_ + g) * D_ + d] = r;
        }
    }
}

// ============================================================
extern "C" void kernel_launch(void* const* d_in, const int* in_sizes, int n_in,
                              void* d_out, int out_size) {
    const int*   position_ids  = (const int*)  d_in[0];
    const float* hidden_states = (const float*)d_in[1];
    float*       k_buffer      = (float*)      d_in[2];
    float*       v_buffer      = (float*)      d_in[3];
    const int*   out_cache_loc = (const int*)  d_in[4];
    const float* wqkv          = (const float*)d_in[5];
    const float* wo            = (const float*)d_in[6];
    const float* q_norm_w      = (const float*)d_in[7];
    const float* k_norm_w      = (const float*)d_in[8];
    float* out = (float*)d_out;

    float* part_ptr; cudaGetSymbolAddress((void**)&part_ptr, g_part);
    float* o_ptr;    cudaGetSymbolAddress((void**)&o_ptr, g_o);

    // 1. QKV projection, split-K partials
    gemm_splitk<<<dim3(QKVN / 128, SPLITK), 256>>>(hidden_states, wqkv, part_ptr, QKVN, H_);
    // 2. reduce + per-head RMSNorm + RoPE + scatter
    norm_rope_scatter<<<dim3(NH_ + 2 * NKV_, B_), 128>>>(
        q_norm_w, k_norm_w, position_ids, out_cache_loc, k_buffer, v_buffer);
    // 3. QK scores
    scores_kernel<<<dim3(KV_ / 512, NKV_, B_), 256>>>(k_buffer);
    // 4. fused softmax + PV
    softmax_pv_kernel<<<dim3(NKV_, B_), 512>>>(v_buffer);
    // 5. output projection, split-K partials, then reduce into d_out
    gemm_splitk<<<dim3(H_ / 128, SPLITK), 256>>>(o_ptr, wo, part_ptr, H_, H_);
    reduce_out<<<(B_ * H_ / 4 + 255) / 256, 256>>>(out, B_ * H_ / 4);
}

// round 3
// speedup vs baseline: 2.9200x; 1.1819x over previous
#include <cuda_runtime.h>
#include <math.h>

#define B_   32
#define KV_  4096
#define H_   4096
#define NH_  32
#define NKV_ 8
#define D_   128
#define G_   4
#define QKVN ((NH_ + 2*NKV_) * D_)   // 6144
#define SCALE_ 0.08838834764831845f  // 128^-0.5
#define SPLITK 8
#define NCHUNK 8
#define CS     (KV_ / NCHUNK)        // 512 slots per chunk

// ---- scratch (device globals: no allocation) ----
__device__ float g_qkv[B_ * QKVN];                       // roped q
__device__ float g_part[SPLITK * B_ * QKVN];             // split-K GEMM partials
__device__ float g_opart[NCHUNK * B_ * NKV_ * G_ * D_];  // attn partial o (4 MB)
__device__ float g_ms[NCHUNK * B_ * NKV_ * G_ * 2];      // attn partial (m, sum)
__device__ float g_o[B_ * NH_ * D_];                     // attention output

// ============================================================
// Split-K GEMM: P[s][32][N] = A[32, kslice] * W[N, kslice]^T
// ============================================================
__global__ __launch_bounds__(256) void gemm_splitk(
        const float* __restrict__ A, const float* __restrict__ W,
        float* __restrict__ P, int N, int K) {
    __shared__ float As[32][36];
    __shared__ float Ws[32][132];
    const int tid = threadIdx.x;
    const int tx = tid & 31;
    const int ty = tid >> 5;
    const int n0 = blockIdx.x * 128;
    const int kslice = K / SPLITK;
    const int kbase = blockIdx.y * kslice;

    float acc[4][4];
    #pragma unroll
    for (int i = 0; i < 4; i++)
        #pragma unroll
        for (int j = 0; j < 4; j++) acc[i][j] = 0.f;

    for (int k0 = kbase; k0 < kbase + kslice; k0 += 32) {
        {
            int m = tid >> 3, c = (tid & 7) * 4;
            float4 a = *(const float4*)&A[m * K + k0 + c];
            As[c + 0][m] = a.x; As[c + 1][m] = a.y;
            As[c + 2][m] = a.z; As[c + 3][m] = a.w;
        }
        #pragma unroll
        for (int j = 0; j < 4; j++) {
            int f = tid + j * 256;
            int n = f >> 3, c = (f & 7) * 4;
            float4 w = *(const float4*)&W[(size_t)(n0 + n) * K + k0 + c];
            Ws[c + 0][n] = w.x; Ws[c + 1][n] = w.y;
            Ws[c + 2][n] = w.z; Ws[c + 3][n] = w.w;
        }
        __syncthreads();
        #pragma unroll
        for (int kk = 0; kk < 32; kk++) {
            float4 a4 = *(const float4*)&As[kk][ty * 4];
            float4 b4 = *(const float4*)&Ws[kk][tx * 4];
            float av[4] = {a4.x, a4.y, a4.z, a4.w};
            float bv[4] = {b4.x, b4.y, b4.z, b4.w};
            #pragma unroll
            for (int i = 0; i < 4; i++)
                #pragma unroll
                for (int j = 0; j < 4; j++) acc[i][j] += av[i] * bv[j];
        }
        __syncthreads();
    }
    float* p = P + (size_t)blockIdx.y * 32 * N;
    #pragma unroll
    for (int i = 0; i < 4; i++)
        *(float4*)&p[(ty * 4 + i) * N + n0 + tx * 4] =
            make_float4(acc[i][0], acc[i][1], acc[i][2], acc[i][3]);
}

// reduce split-K partials for the O projection into d_out
__global__ void reduce_out(float* __restrict__ out, int total4) {
    int i = blockIdx.x * blockDim.x + threadIdx.x;
    if (i >= total4) return;
    float4 r = make_float4(0.f, 0.f, 0.f, 0.f);
    #pragma unroll
    for (int s = 0; s < SPLITK; s++) {
        float4 x = *(const float4*)&g_part[(size_t)s * (B_ * H_) + i * 4];
        r.x += x.x; r.y += x.y; r.z += x.z; r.w += x.w;
    }
    ((float4*)out)[i] = r;
}

// ============================================================
// split-K reduce (QKV) + RMSNorm + NeoX RoPE + scatter k,v.
// ============================================================
__global__ void norm_rope_scatter(const float* __restrict__ q_norm_w,
                                  const float* __restrict__ k_norm_w,
                                  const int* __restrict__ position_ids,
                                  const int* __restrict__ out_cache_loc,
                                  float* __restrict__ k_buf,
                                  float* __restrict__ v_buf) {
    const int head = blockIdx.x;
    const int b = blockIdx.y;
    const int tid = threadIdx.x;
    const int off = b * QKVN + head * D_ + tid;

    float x = 0.f;
    #pragma unroll
    for (int s = 0; s < SPLITK; s++) x += g_part[(size_t)s * (B_ * QKVN) + off];

    if (head >= NH_ + NKV_) {
        int h = head - (NH_ + NKV_);
        int loc = out_cache_loc[b];
        v_buf[(((size_t)b * KV_ + loc) * NKV_ + h) * D_ + tid] = x;
        return;
    }

    __shared__ float sred[4];
    float ss = x * x;
    #pragma unroll
    for (int o = 16; o; o >>= 1) ss += __shfl_xor_sync(0xffffffffu, ss, o);
    if ((tid & 31) == 0) sred[tid >> 5] = ss;
    __syncthreads();
    float total = sred[0] + sred[1] + sred[2] + sred[3];
    float rms = rsqrtf(total * (1.0f / D_) + 1e-6f);
    const float* wn = (head < NH_) ? q_norm_w : k_norm_w;
    float y = x * rms * wn[tid];

    __shared__ float ys[128];
    ys[tid] = y;
    __syncthreads();
    int i = tid & 63;
    double invf = pow(1.0e6, -(double)i / 64.0);
    double ang = (double)position_ids[b] * invf;
    float c = (float)cos(ang), s = (float)sin(ang);
    float outv = (tid < 64) ? (ys[tid] * c - ys[tid + 64] * s)
                            : (ys[tid] * c + ys[tid - 64] * s);

    if (head < NH_) {
        g_qkv[off] = outv;
    } else {
        int h = head - NH_;
        int loc = out_cache_loc[b];
        k_buf[(((size_t)b * KV_ + loc) * NKV_ + h) * D_ + tid] = outv;
    }
}

// ============================================================
// Fused flash-decode chunk: scores + local softmax + PV partial.
// grid (chunk=8, h=8, b=32), 256 threads.
// Emits unnormalized partial o and (m_local, sum_local) per g.
// ============================================================
__global__ __launch_bounds__(256) void attn_chunk_kernel(
        const float* __restrict__ k_buf, const float* __restrict__ v_buf) {
    const int chunk = blockIdx.x, h = blockIdx.y, b = blockIdx.z;
    const int tid = threadIdx.x;
    const int warp = tid >> 5, lane = tid & 31;

    __shared__ float sc[G_][CS];       // scores -> exp values (8 KB)
    __shared__ float wred[G_][8];      // per-warp reduction staging
    __shared__ float gm[G_], gs[G_];

    // ---- scores: warp per slot, 4 g-heads share the K load ----
    float4 q4[G_];
    #pragma unroll
    for (int g = 0; g < G_; g++)
        q4[g] = *(const float4*)&g_qkv[b * QKVN + (h * G_ + g) * D_ + lane * 4];

    const int s0 = chunk * CS;
    #pragma unroll 2
    for (int i = warp; i < CS; i += 8) {
        float4 kv = *(const float4*)&k_buf[(((size_t)b * KV_ + s0 + i) * NKV_ + h) * D_ + lane * 4];
        float p[G_];
        #pragma unroll
        for (int g = 0; g < G_; g++)
            p[g] = q4[g].x * kv.x + q4[g].y * kv.y + q4[g].z * kv.z + q4[g].w * kv.w;
        #pragma unroll
        for (int g = 0; g < G_; g++)
            #pragma unroll
            for (int o = 16; o; o >>= 1) p[g] += __shfl_xor_sync(0xffffffffu, p[g], o);
        if (lane == 0) {
            #pragma unroll
            for (int g = 0; g < G_; g++) sc[g][i] = p[g] * SCALE_;
        }
    }
    __syncthreads();

    // ---- local softmax stats: 64 threads (2 warps) per g ----
    {
        const int g = tid >> 6;          // 0..3
        const int j = tid & 63;
        float m = -1e30f;
        #pragma unroll
        for (int e = 0; e < CS / 64; e++) m = fmaxf(m, sc[g][j + e * 64]);
        #pragma unroll
        for (int o = 16; o; o >>= 1) m = fmaxf(m, __shfl_xor_sync(0xffffffffu, m, o));
        if (lane == 0) wred[g][warp & 1] = m;
        __syncthreads();
        m = fmaxf(wred[g][0], wred[g][1]);

        float sum = 0.f;
        #pragma unroll
        for (int e = 0; e < CS / 64; e++) {
            float ex = __expf(sc[g][j + e * 64] - m);
            sc[g][j + e * 64] = ex;
            sum += ex;
        }
        #pragma unroll
        for (int o = 16; o; o >>= 1) sum += __shfl_xor_sync(0xffffffffu, sum, o);
        if (lane == 0) wred[g][2 + (warp & 1)] = sum;
        __syncthreads();
        if (j == 0) { gm[g] = m; gs[g] = wred[g][2] + wred[g][3]; }
    }
    __syncthreads();

    // ---- PV partial: thread d = tid&127, half = tid>>7 covers 256 slots ----
    const int d = tid & 127;
    const int half = tid >> 7;
    float acc[G_] = {0.f, 0.f, 0.f, 0.f};
    const size_t vbase = (((size_t)b * KV_ + s0 + half * 256) * NKV_ + h) * D_ + d;

    #pragma unroll 8
    for (int sl = 0; sl < 256; sl++) {
        float v = v_buf[vbase + (size_t)sl * (NKV_ * D_)];
        #pragma unroll
        for (int g = 0; g < G_; g++) acc[g] += sc[g][half * 256 + sl] * v;
    }
    __syncthreads();

    // combine the two halves via smem (reuse sc storage)
    float (*psh)[D_] = (float(*)[D_])sc;   // [half*4+g][d]
    #pragma unroll
    for (int g = 0; g < G_; g++) psh[half * G_ + g][d] = acc[g];
    __syncthreads();

    if (half == 0) {
        const size_t obase = ((((size_t)chunk * B_ + b) * NKV_ + h) * G_) * D_;
        #pragma unroll
        for (int g = 0; g < G_; g++)
            g_opart[obase + g * D_ + d] = psh[g][d] + psh[G_ + g][d];
        if (d < G_) {
            size_t msb = ((((size_t)chunk * B_ + b) * NKV_ + h) * G_ + d) * 2;
            g_ms[msb] = gm[d];
            g_ms[msb + 1] = gs[d];
        }
    }
}

// ============================================================
// Combine chunk partials: grid (h=8, b=32), 128 threads (d).
// ============================================================
__global__ void attn_combine_kernel() {
    const int h = blockIdx.x, b = blockIdx.y;
    const int d = threadIdx.x;

    #pragma unroll
    for (int g = 0; g < G_; g++) {
        float M = -1e30f;
        float mloc[NCHUNK];
        #pragma unroll
        for (int c = 0; c < NCHUNK; c++) {
            size_t msb = ((((size_t)c * B_ + b) * NKV_ + h) * G_ + g) * 2;
            mloc[c] = g_ms[msb];
            M = fmaxf(M, mloc[c]);
        }
        float S = 0.f, o = 0.f;
        #pragma unroll
        for (int c = 0; c < NCHUNK; c++) {
            size_t msb = ((((size_t)c * B_ + b) * NKV_ + h) * G_ + g) * 2;
            float w = __expf(mloc[c] - M);
            S += g_ms[msb + 1] * w;
            o += g_opart[(((((size_t)c * B_ + b) * NKV_ + h) * G_ + g)) * D_ + d] * w;
        }
        g_o[b * (NH_ * D_) + (h * G_ + g) * D_ + d] = o / S;
    }
}

// ============================================================
extern "C" void kernel_launch(void* const* d_in, const int* in_sizes, int n_in,
                              void* d_out, int out_size) {
    const int*   position_ids  = (const int*)  d_in[0];
    const float* hidden_states = (const float*)d_in[1];
    float*       k_buffer      = (float*)      d_in[2];
    float*       v_buffer      = (float*)      d_in[3];
    const int*   out_cache_loc = (const int*)  d_in[4];
    const float* wqkv          = (const float*)d_in[5];
    const float* wo            = (const float*)d_in[6];
    const float* q_norm_w      = (const float*)d_in[7];
    const float* k_norm_w      = (const float*)d_in[8];
    float* out = (float*)d_out;

    float* part_ptr; cudaGetSymbolAddress((void**)&part_ptr, g_part);
    float* o_ptr;    cudaGetSymbolAddress((void**)&o_ptr, g_o);

    // 1. QKV projection (split-K partials)
    gemm_splitk<<<dim3(QKVN / 128, SPLITK), 256>>>(hidden_states, wqkv, part_ptr, QKVN, H_);
    // 2. reduce + RMSNorm + RoPE + scatter
    norm_rope_scatter<<<dim3(NH_ + 2 * NKV_, B_), 128>>>(
        q_norm_w, k_norm_w, position_ids, out_cache_loc, k_buffer, v_buffer);
    // 3. fused flash-decode (split-KV)
    attn_chunk_kernel<<<dim3(NCHUNK, NKV_, B_), 256>>>(k_buffer, v_buffer);
    // 4. combine partials
    attn_combine_kernel<<<dim3(NKV_, B_), 128>>>();
    // 5. O projection + reduce
    gemm_splitk<<<dim3(H_ / 128, SPLITK), 256>>>(o_ptr, wo, part_ptr, H_, H_);
    reduce_out<<<(B_ * H_ / 4 + 255) / 256, 256>>>(out, B_ * H_ / 4);
}

// round 5
// speedup vs baseline: 3.2248x; 1.1044x over previous
#include <cuda_runtime.h>
#include <math.h>

#define B_   32
#define KV_  4096
#define H_   4096
#define NH_  32
#define NKV_ 8
#define D_   128
#define G_   4
#define QKVN ((NH_ + 2*NKV_) * D_)   // 6144
#define SCALE_ 0.08838834764831845f  // 128^-0.5
#define SPLITK 8
#define NCHUNK 16
#define CS     (KV_ / NCHUNK)        // 256 slots per chunk

// ---- scratch (device globals: no allocation) ----
__device__ float g_qkv[B_ * QKVN];                       // roped q
__device__ float g_part[SPLITK * B_ * QKVN];             // split-K GEMM partials
__device__ float g_opart[NCHUNK * B_ * NKV_ * G_ * D_];  // attn partial o (8 MB)
__device__ float g_ms[NCHUNK * B_ * NKV_ * G_ * 2];      // attn partial (m, sum)
__device__ float g_o[B_ * NH_ * D_];                     // attention output

// ============================================================
// Split-K GEMM with register-prefetch double buffering.
// P[s][32][N] = A[32, kslice] * W[N, kslice]^T
// ============================================================
__global__ __launch_bounds__(256) void gemm_splitk(
        const float* __restrict__ A, const float* __restrict__ W,
        float* __restrict__ P, int N, int K) {
    __shared__ float As[32][36];
    __shared__ float Ws[32][132];
    const int tid = threadIdx.x;
    const int tx = tid & 31;
    const int ty = tid >> 5;
    const int n0 = blockIdx.x * 128;
    const int kslice = K / SPLITK;
    const int kbase = blockIdx.y * kslice;

    const int m_a = tid >> 3, c_a = (tid & 7) * 4;
    const float* Aptr = &A[m_a * K + kbase + c_a];
    const float* Wptr[4];
    int n_w[4], c_w[4];
    #pragma unroll
    for (int j = 0; j < 4; j++) {
        int f = tid + j * 256;
        n_w[j] = f >> 3; c_w[j] = (f & 7) * 4;
        Wptr[j] = &W[(size_t)(n0 + n_w[j]) * K + kbase + c_w[j]];
    }

    float acc[4][4];
    #pragma unroll
    for (int i = 0; i < 4; i++)
        #pragma unroll
        for (int j = 0; j < 4; j++) acc[i][j] = 0.f;

    // prefetch chunk 0
    float4 a_reg = *(const float4*)Aptr;
    float4 w_reg[4];
    #pragma unroll
    for (int j = 0; j < 4; j++) w_reg[j] = *(const float4*)Wptr[j];

    const int nchunks = kslice / 32;
    for (int ck = 0; ck < nchunks; ck++) {
        As[c_a + 0][m_a] = a_reg.x; As[c_a + 1][m_a] = a_reg.y;
        As[c_a + 2][m_a] = a_reg.z; As[c_a + 3][m_a] = a_reg.w;
        #pragma unroll
        for (int j = 0; j < 4; j++) {
            Ws[c_w[j] + 0][n_w[j]] = w_reg[j].x;
            Ws[c_w[j] + 1][n_w[j]] = w_reg[j].y;
            Ws[c_w[j] + 2][n_w[j]] = w_reg[j].z;
            Ws[c_w[j] + 3][n_w[j]] = w_reg[j].w;
        }
        __syncthreads();

        if (ck + 1 < nchunks) {
            a_reg = *(const float4*)(Aptr + (ck + 1) * 32);
            #pragma unroll
            for (int j = 0; j < 4; j++)
                w_reg[j] = *(const float4*)(Wptr[j] + (ck + 1) * 32);
        }

        #pragma unroll
        for (int kk = 0; kk < 32; kk++) {
            float4 a4 = *(const float4*)&As[kk][ty * 4];
            float4 b4 = *(const float4*)&Ws[kk][tx * 4];
            float av[4] = {a4.x, a4.y, a4.z, a4.w};
            float bv[4] = {b4.x, b4.y, b4.z, b4.w};
            #pragma unroll
            for (int i = 0; i < 4; i++)
                #pragma unroll
                for (int j = 0; j < 4; j++) acc[i][j] += av[i] * bv[j];
        }
        __syncthreads();
    }
    float* p = P + (size_t)blockIdx.y * 32 * N;
    #pragma unroll
    for (int i = 0; i < 4; i++)
        *(float4*)&p[(ty * 4 + i) * N + n0 + tx * 4] =
            make_float4(acc[i][0], acc[i][1], acc[i][2], acc[i][3]);
}

// reduce split-K partials for the O projection into d_out
__global__ void reduce_out(float* __restrict__ out, int total4) {
    int i = blockIdx.x * blockDim.x + threadIdx.x;
    if (i >= total4) return;
    float4 r = make_float4(0.f, 0.f, 0.f, 0.f);
    #pragma unroll
    for (int s = 0; s < SPLITK; s++) {
        float4 x = *(const float4*)&g_part[(size_t)s * (B_ * H_) + i * 4];
        r.x += x.x; r.y += x.y; r.z += x.z; r.w += x.w;
    }
    ((float4*)out)[i] = r;
}

// ============================================================
// split-K reduce (QKV) + RMSNorm + NeoX RoPE + scatter k,v.
// ============================================================
__global__ void norm_rope_scatter(const float* __restrict__ q_norm_w,
                                  const float* __restrict__ k_norm_w,
                                  const int* __restrict__ position_ids,
                                  const int* __restrict__ out_cache_loc,
                                  float* __restrict__ k_buf,
                                  float* __restrict__ v_buf) {
    const int head = blockIdx.x;
    const int b = blockIdx.y;
    const int tid = threadIdx.x;
    const int off = b * QKVN + head * D_ + tid;

    float x = 0.f;
    #pragma unroll
    for (int s = 0; s < SPLITK; s++) x += g_part[(size_t)s * (B_ * QKVN) + off];

    if (head >= NH_ + NKV_) {
        int h = head - (NH_ + NKV_);
        int loc = out_cache_loc[b];
        v_buf[(((size_t)b * KV_ + loc) * NKV_ + h) * D_ + tid] = x;
        return;
    }

    __shared__ float sred[4];
    float ss = x * x;
    #pragma unroll
    for (int o = 16; o; o >>= 1) ss += __shfl_xor_sync(0xffffffffu, ss, o);
    if ((tid & 31) == 0) sred[tid >> 5] = ss;
    __syncthreads();
    float total = sred[0] + sred[1] + sred[2] + sred[3];
    float rms = rsqrtf(total * (1.0f / D_) + 1e-6f);
    const float* wn = (head < NH_) ? q_norm_w : k_norm_w;
    float y = x * rms * wn[tid];

    __shared__ float ys[128];
    ys[tid] = y;
    __syncthreads();
    int i = tid & 63;
    double invf = pow(1.0e6, -(double)i / 64.0);
    double ang = (double)position_ids[b] * invf;
    float c = (float)cos(ang), s = (float)sin(ang);
    float outv = (tid < 64) ? (ys[tid] * c - ys[tid + 64] * s)
                            : (ys[tid] * c + ys[tid - 64] * s);

    if (head < NH_) {
        g_qkv[off] = outv;
    } else {
        int h = head - NH_;
        int loc = out_cache_loc[b];
        k_buf[(((size_t)b * KV_ + loc) * NKV_ + h) * D_ + tid] = outv;
    }
}

// ============================================================
// Fused flash-decode chunk: scores + local softmax + PV partial.
// grid (chunk=16, h=8, b=32) = 4096 blocks, 256 threads.
// ============================================================
__global__ __launch_bounds__(256) void attn_chunk_kernel(
        const float* __restrict__ k_buf, const float* __restrict__ v_buf) {
    const int chunk = blockIdx.x, h = blockIdx.y, b = blockIdx.z;
    const int tid = threadIdx.x;
    const int warp = tid >> 5, lane = tid & 31;

    // 8 KB buffer, aliased by phase:
    //   phase 1-2: sc[G_][CS]            (4 KB used)
    //   phase 3  : psh[4][G_][64] float2 (8 KB used)
    __shared__ float sbuf[4 * G_ * 64 * 2];
    float (*sc)[CS] = (float(*)[CS])sbuf;
    __shared__ float wred[G_][8];
    __shared__ float gm[G_], gs[G_];

    // ---- scores: warp per slot, 4 g-heads share the K load ----
    float4 q4[G_];
    #pragma unroll
    for (int g = 0; g < G_; g++)
        q4[g] = *(const float4*)&g_qkv[b * QKVN + (h * G_ + g) * D_ + lane * 4];

    const int s0 = chunk * CS;
    #pragma unroll 4
    for (int i = warp; i < CS; i += 8) {
        float4 kv = *(const float4*)&k_buf[(((size_t)b * KV_ + s0 + i) * NKV_ + h) * D_ + lane * 4];
        float p[G_];
        #pragma unroll
        for (int g = 0; g < G_; g++)
            p[g] = q4[g].x * kv.x + q4[g].y * kv.y + q4[g].z * kv.z + q4[g].w * kv.w;
        #pragma unroll
        for (int g = 0; g < G_; g++)
            #pragma unroll
            for (int o = 16; o; o >>= 1) p[g] += __shfl_xor_sync(0xffffffffu, p[g], o);
        if (lane == 0) {
            #pragma unroll
            for (int g = 0; g < G_; g++) sc[g][i] = p[g] * SCALE_;
        }
    }
    __syncthreads();

    // ---- local softmax stats: 64 threads (2 warps) per g ----
    {
        const int g = tid >> 6;
        const int j = tid & 63;
        float m = -1e30f;
        #pragma unroll
        for (int e = 0; e < CS / 64; e++) m = fmaxf(m, sc[g][j + e * 64]);
        #pragma unroll
        for (int o = 16; o; o >>= 1) m = fmaxf(m, __shfl_xor_sync(0xffffffffu, m, o));
        if (lane == 0) wred[g][warp & 1] = m;
        __syncthreads();
        m = fmaxf(wred[g][0], wred[g][1]);

        float sum = 0.f;
        #pragma unroll
        for (int e = 0; e < CS / 64; e++) {
            float ex = __expf(sc[g][j + e * 64] - m);
            sc[g][j + e * 64] = ex;
            sum += ex;
        }
        #pragma unroll
        for (int o = 16; o; o >>= 1) sum += __shfl_xor_sync(0xffffffffu, sum, o);
        if (lane == 0) wred[g][2 + (warp & 1)] = sum;
        __syncthreads();
        if (j == 0) { gm[g] = m; gs[g] = wred[g][2] + wred[g][3]; }
    }
    __syncthreads();

    // ---- PV partial: thread owns dims (2*d2, 2*d2+1); quarter covers 64 slots ----
    const int d2 = tid & 63;
    const int q = tid >> 6;          // 0..3
    float2 acc[G_];
    #pragma unroll
    for (int g = 0; g < G_; g++) acc[g] = make_float2(0.f, 0.f);
    float pv[G_];                    // snapshot exp values before sbuf is re-aliased

    const float* vp = &v_buf[(((size_t)b * KV_ + s0 + q * 64) * NKV_ + h) * D_ + d2 * 2];
    #pragma unroll 8
    for (int sl = 0; sl < 64; sl++) {
        float2 v = *(const float2*)(vp + (size_t)sl * (NKV_ * D_));
        #pragma unroll
        for (int g = 0; g < G_; g++) {
            float p = sc[g][q * 64 + sl];
            acc[g].x += p * v.x;
            acc[g].y += p * v.y;
        }
    }
    (void)pv;
    __syncthreads();   // all reads of sc done before re-alias

    // combine the four quarters via smem (re-alias sbuf: 8 KB)
    float2 (*psh)[G_][64] = (float2(*)[G_][64])sbuf;   // [q][g][d2]
    #pragma unroll
    for (int g = 0; g < G_; g++) psh[q][g][d2] = acc[g];
    __syncthreads();

    if (q == 0) {
        const size_t obase = ((((size_t)chunk * B_ + b) * NKV_ + h) * G_) * D_;
        #pragma unroll
        for (int g = 0; g < G_; g++) {
            float2 r0 = psh[0][g][d2], r1 = psh[1][g][d2];
            float2 r2 = psh[2][g][d2], r3 = psh[3][g][d2];
            float2 r = make_float2(r0.x + r1.x + r2.x + r3.x,
                                   r0.y + r1.y + r2.y + r3.y);
            *(float2*)&g_opart[obase + g * D_ + d2 * 2] = r;
        }
        if (d2 < G_) {
            size_t msb = ((((size_t)chunk * B_ + b) * NKV_ + h) * G_ + d2) * 2;
            g_ms[msb] = gm[d2];
            g_ms[msb + 1] = gs[d2];
        }
    }
}

// ============================================================
// Combine chunk partials: grid (NH=32, b=32) = 1024 blocks, 128 threads.
// ============================================================
__global__ void attn_combine_kernel() {
    const int head = blockIdx.x;            // 0..31 (= h*G + g)
    const int b = blockIdx.y;
    const int h = head >> 2, g = head & 3;
    const int d = threadIdx.x;

    float M = -1e30f;
    float mloc[NCHUNK];
    #pragma unroll
    for (int c = 0; c < NCHUNK; c++) {
        size_t msb = ((((size_t)c * B_ + b) * NKV_ + h) * G_ + g) * 2;
        mloc[c] = g_ms[msb];
        M = fmaxf(M, mloc[c]);
    }
    float S = 0.f, o = 0.f;
    #pragma unroll
    for (int c = 0; c < NCHUNK; c++) {
        size_t msb = ((((size_t)c * B_ + b) * NKV_ + h) * G_ + g) * 2;
        float w = __expf(mloc[c] - M);
        S += g_ms[msb + 1] * w;
        o += g_opart[(((((size_t)c * B_ + b) * NKV_ + h) * G_ + g)) * D_ + d] * w;
    }
    g_o[b * (NH_ * D_) + head * D_ + d] = o / S;
}

// ============================================================
extern "C" void kernel_launch(void* const* d_in, const int* in_sizes, int n_in,
                              void* d_out, int out_size) {
    const int*   position_ids  = (const int*)  d_in[0];
    const float* hidden_states = (const float*)d_in[1];
    float*       k_buffer      = (float*)      d_in[2];
    float*       v_buffer      = (float*)      d_in[3];
    const int*   out_cache_loc = (const int*)  d_in[4];
    const float* wqkv          = (const float*)d_in[5];
    const float* wo            = (const float*)d_in[6];
    const float* q_norm_w      = (const float*)d_in[7];
    const float* k_norm_w      = (const float*)d_in[8];
    float* out = (float*)d_out;

    float* part_ptr; cudaGetSymbolAddress((void**)&part_ptr, g_part);
    float* o_ptr;    cudaGetSymbolAddress((void**)&o_ptr, g_o);

    // 1. QKV projection (split-K partials)
    gemm_splitk<<<dim3(QKVN / 128, SPLITK), 256>>>(hidden_states, wqkv, part_ptr, QKVN, H_);
    // 2. reduce + RMSNorm + RoPE + scatter
    norm_rope_scatter<<<dim3(NH_ + 2 * NKV_, B_), 128>>>(
        q_norm_w, k_norm_w, position_ids, out_cache_loc, k_buffer, v_buffer);
    // 3. fused flash-decode (split-KV)
    attn_chunk_kernel<<<dim3(NCHUNK, NKV_, B_), 256>>>(k_buffer, v_buffer);
    // 4. combine partials
    attn_combine_kernel<<<dim3(NH_, B_), 128>>>();
    // 5. O projection + reduce
    gemm_splitk<<<dim3(H_ / 128, SPLITK), 256>>>(o_ptr, wo, part_ptr, H_, H_);
    reduce_out<<<(B_ * H_ / 4 + 255) / 256, 256>>>(out, B_ * H_ / 4);
}

// round 6
// speedup vs baseline: 3.2251x; 1.0001x over previous
#include <cuda_runtime.h>
#include <math.h>

#define B_   32
#define KV_  4096
#define H_   4096
#define NH_  32
#define NKV_ 8
#define D_   128
#define G_   4
#define QKVN ((NH_ + 2*NKV_) * D_)   // 6144
#define SCALE_ 0.08838834764831845f  // 128^-0.5
#define SPLITK 8
#define NCHUNK 16
#define CS     (KV_ / NCHUNK)        // 256 slots per chunk

// ---- scratch (device globals: no allocation) ----
__device__ float g_qkv[B_ * QKVN];                       // roped q
__device__ float g_part[SPLITK * B_ * QKVN];             // split-K GEMM partials
__device__ float g_opart[NCHUNK * B_ * NKV_ * G_ * D_];  // attn partial o
__device__ float g_ms[NCHUNK * B_ * NKV_ * G_ * 2];      // attn partial (m, sum)
__device__ float g_o[B_ * NH_ * D_];                     // attention output

__device__ __forceinline__ float f2tf32(float x) {
    unsigned u;
    asm("cvt.rna.tf32.f32 %0, %1;" : "=r"(u) : "f"(x));
    return __uint_as_float(u);
}

// ============================================================
// TF32 split-K GEMM: P[s][32][N] = A[32,kslice] * W[N,kslice]^T
// block tile 32(M) x 64(N), k-chunk 32, 256 threads (8 warps).
// warp w: m-half = w&1, n-quarter = w>>1 (16 cols = 2 mma n-subtiles).
// mma.sync.aligned.m16n8k8.row.col.f32.tf32.tf32.f32
// ============================================================
__global__ __launch_bounds__(256) void gemm_tf32(
        const float* __restrict__ A, const float* __restrict__ W,
        float* __restrict__ P, int N, int K) {
    __shared__ float As[32][40];    // [k][m], stride 40 -> conflict-free frags
    __shared__ float Ws[32][136];   // [k][n], stride 136
    const int tid = threadIdx.x;
    const int warp = tid >> 5, lane = tid & 31;
    const int mt = warp & 1;        // m half (16 rows)
    const int nq = warp >> 1;       // n quarter (16 cols)
    const int gi = lane >> 2, ti = lane & 3;
    const int n0 = blockIdx.x * 64;
    const int kslice = K / SPLITK;
    const int kbase = blockIdx.y * kslice;

    // global load addressing: A chunk 32x32 (1 float4/thread), W chunk 64x32 (2)
    const int m_a = tid >> 3, c_a = (tid & 7) * 4;
    const float* Aptr = &A[m_a * K + kbase + c_a];
    const float* Wptr[2];
    int n_w[2], c_w[2];
    #pragma unroll
    for (int j = 0; j < 2; j++) {
        int f = tid + j * 256;
        n_w[j] = f >> 3; c_w[j] = (f & 7) * 4;
        Wptr[j] = &W[(size_t)(n0 + n_w[j]) * K + kbase + c_w[j]];
    }

    float d[2][4];
    #pragma unroll
    for (int s = 0; s < 2; s++)
        #pragma unroll
        for (int i = 0; i < 4; i++) d[s][i] = 0.f;

    // prefetch chunk 0
    float4 a_reg = *(const float4*)Aptr;
    float4 w_reg[2];
    #pragma unroll
    for (int j = 0; j < 2; j++) w_reg[j] = *(const float4*)Wptr[j];

    const int nchunks = kslice / 32;
    for (int ck = 0; ck < nchunks; ck++) {
        As[c_a + 0][m_a] = f2tf32(a_reg.x); As[c_a + 1][m_a] = f2tf32(a_reg.y);
        As[c_a + 2][m_a] = f2tf32(a_reg.z); As[c_a + 3][m_a] = f2tf32(a_reg.w);
        #pragma unroll
        for (int j = 0; j < 2; j++) {
            Ws[c_w[j] + 0][n_w[j]] = f2tf32(w_reg[j].x);
            Ws[c_w[j] + 1][n_w[j]] = f2tf32(w_reg[j].y);
            Ws[c_w[j] + 2][n_w[j]] = f2tf32(w_reg[j].z);
            Ws[c_w[j] + 3][n_w[j]] = f2tf32(w_reg[j].w);
        }
        __syncthreads();

        if (ck + 1 < nchunks) {
            a_reg = *(const float4*)(Aptr + (ck + 1) * 32);
            #pragma unroll
            for (int j = 0; j < 2; j++)
                w_reg[j] = *(const float4*)(Wptr[j] + (ck + 1) * 32);
        }

        #pragma unroll
        for (int kk = 0; kk < 4; kk++) {
            const int k0 = kk * 8;
            const int r0 = mt * 16 + gi;
            unsigned a0 = __float_as_uint(As[k0 + ti][r0]);
            unsigned a1 = __float_as_uint(As[k0 + ti][r0 + 8]);
            unsigned a2 = __float_as_uint(As[k0 + ti + 4][r0]);
            unsigned a3 = __float_as_uint(As[k0 + ti + 4][r0 + 8]);
            #pragma unroll
            for (int s = 0; s < 2; s++) {
                const int nb = nq * 16 + s * 8;
                unsigned b0 = __float_as_uint(Ws[k0 + ti][nb + gi]);
                unsigned b1 = __float_as_uint(Ws[k0 + ti + 4][nb + gi]);
                asm volatile(
                    "mma.sync.aligned.m16n8k8.row.col.f32.tf32.tf32.f32 "
                    "{%0,%1,%2,%3}, {%4,%5,%6,%7}, {%8,%9}, {%0,%1,%2,%3};\n"
                    : "+f"(d[s][0]), "+f"(d[s][1]), "+f"(d[s][2]), "+f"(d[s][3])
                    : "r"(a0), "r"(a1), "r"(a2), "r"(a3), "r"(b0), "r"(b1));
            }
        }
        __syncthreads();
    }

    // write-out: c0/c1 -> (row, 2t/2t+1), c2/c3 -> (row+8, ...)
    float* p = P + (size_t)blockIdx.y * 32 * N;
    const int row = mt * 16 + gi;
    #pragma unroll
    for (int s = 0; s < 2; s++) {
        const int col = n0 + nq * 16 + s * 8 + ti * 2;
        *(float2*)&p[row * N + col] = make_float2(d[s][0], d[s][1]);
        *(float2*)&p[(row + 8) * N + col] = make_float2(d[s][2], d[s][3]);
    }
}

// reduce split-K partials for the O projection into d_out
__global__ void reduce_out(float* __restrict__ out, int total4) {
    int i = blockIdx.x * blockDim.x + threadIdx.x;
    if (i >= total4) return;
    float4 r = make_float4(0.f, 0.f, 0.f, 0.f);
    #pragma unroll
    for (int s = 0; s < SPLITK; s++) {
        float4 x = *(const float4*)&g_part[(size_t)s * (B_ * H_) + i * 4];
        r.x += x.x; r.y += x.y; r.z += x.z; r.w += x.w;
    }
    ((float4*)out)[i] = r;
}

// ============================================================
// split-K reduce (QKV) + RMSNorm + NeoX RoPE + scatter k,v.
// ============================================================
__global__ void norm_rope_scatter(const float* __restrict__ q_norm_w,
                                  const float* __restrict__ k_norm_w,
                                  const int* __restrict__ position_ids,
                                  const int* __restrict__ out_cache_loc,
                                  float* __restrict__ k_buf,
                                  float* __restrict__ v_buf) {
    const int head = blockIdx.x;
    const int b = blockIdx.y;
    const int tid = threadIdx.x;
    const int off = b * QKVN + head * D_ + tid;

    float x = 0.f;
    #pragma unroll
    for (int s = 0; s < SPLITK; s++) x += g_part[(size_t)s * (B_ * QKVN) + off];

    if (head >= NH_ + NKV_) {
        int h = head - (NH_ + NKV_);
        int loc = out_cache_loc[b];
        v_buf[(((size_t)b * KV_ + loc) * NKV_ + h) * D_ + tid] = x;
        return;
    }

    __shared__ float sred[4];
    float ss = x * x;
    #pragma unroll
    for (int o = 16; o; o >>= 1) ss += __shfl_xor_sync(0xffffffffu, ss, o);
    if ((tid & 31) == 0) sred[tid >> 5] = ss;
    __syncthreads();
    float total = sred[0] + sred[1] + sred[2] + sred[3];
    float rms = rsqrtf(total * (1.0f / D_) + 1e-6f);
    const float* wn = (head < NH_) ? q_norm_w : k_norm_w;
    float y = x * rms * wn[tid];

    __shared__ float ys[128];
    ys[tid] = y;
    __syncthreads();
    int i = tid & 63;
    double invf = pow(1.0e6, -(double)i / 64.0);
    double ang = (double)position_ids[b] * invf;
    float c = (float)cos(ang), s = (float)sin(ang);
    float outv = (tid < 64) ? (ys[tid] * c - ys[tid + 64] * s)
                            : (ys[tid] * c + ys[tid - 64] * s);

    if (head < NH_) {
        g_qkv[off] = outv;
    } else {
        int h = head - NH_;
        int loc = out_cache_loc[b];
        k_buf[(((size_t)b * KV_ + loc) * NKV_ + h) * D_ + tid] = outv;
    }
}

// ============================================================
// Fused flash-decode chunk: scores + local softmax + PV partial.
// grid (chunk=16, h=8, b=32) = 4096 blocks, 256 threads.
// ============================================================
__global__ __launch_bounds__(256) void attn_chunk_kernel(
        const float* __restrict__ k_buf, const float* __restrict__ v_buf) {
    const int chunk = blockIdx.x, h = blockIdx.y, b = blockIdx.z;
    const int tid = threadIdx.x;
    const int warp = tid >> 5, lane = tid & 31;

    // 8 KB buffer aliased by phase (sc: 4 KB, psh: 8 KB)
    __shared__ float sbuf[4 * G_ * 64 * 2];
    float (*sc)[CS] = (float(*)[CS])sbuf;
    __shared__ float wred[G_][8];
    __shared__ float gm[G_], gs[G_];

    float4 q4[G_];
    #pragma unroll
    for (int g = 0; g < G_; g++)
        q4[g] = *(const float4*)&g_qkv[b * QKVN + (h * G_ + g) * D_ + lane * 4];

    const int s0 = chunk * CS;
    #pragma unroll 4
    for (int i = warp; i < CS; i += 8) {
        float4 kv = *(const float4*)&k_buf[(((size_t)b * KV_ + s0 + i) * NKV_ + h) * D_ + lane * 4];
        float p[G_];
        #pragma unroll
        for (int g = 0; g < G_; g++)
            p[g] = q4[g].x * kv.x + q4[g].y * kv.y + q4[g].z * kv.z + q4[g].w * kv.w;
        #pragma unroll
        for (int g = 0; g < G_; g++)
            #pragma unroll
            for (int o = 16; o; o >>= 1) p[g] += __shfl_xor_sync(0xffffffffu, p[g], o);
        if (lane == 0) {
            #pragma unroll
            for (int g = 0; g < G_; g++) sc[g][i] = p[g] * SCALE_;
        }
    }
    __syncthreads();

    {
        const int g = tid >> 6;
        const int j = tid & 63;
        float m = -1e30f;
        #pragma unroll
        for (int e = 0; e < CS / 64; e++) m = fmaxf(m, sc[g][j + e * 64]);
        #pragma unroll
        for (int o = 16; o; o >>= 1) m = fmaxf(m, __shfl_xor_sync(0xffffffffu, m, o));
        if (lane == 0) wred[g][warp & 1] = m;
        __syncthreads();
        m = fmaxf(wred[g][0], wred[g][1]);

        float sum = 0.f;
        #pragma unroll
        for (int e = 0; e < CS / 64; e++) {
            float ex = __expf(sc[g][j + e * 64] - m);
            sc[g][j + e * 64] = ex;
            sum += ex;
        }
        #pragma unroll
        for (int o = 16; o; o >>= 1) sum += __shfl_xor_sync(0xffffffffu, sum, o);
        if (lane == 0) wred[g][2 + (warp & 1)] = sum;
        __syncthreads();
        if (j == 0) { gm[g] = m; gs[g] = wred[g][2] + wred[g][3]; }
    }
    __syncthreads();

    const int d2 = tid & 63;
    const int q = tid >> 6;
    float2 acc[G_];
    #pragma unroll
    for (int g = 0; g < G_; g++) acc[g] = make_float2(0.f, 0.f);

    const float* vp = &v_buf[(((size_t)b * KV_ + s0 + q * 64) * NKV_ + h) * D_ + d2 * 2];
    #pragma unroll 8
    for (int sl = 0; sl < 64; sl++) {
        float2 v = *(const float2*)(vp + (size_t)sl * (NKV_ * D_));
        #pragma unroll
        for (int g = 0; g < G_; g++) {
            float p = sc[g][q * 64 + sl];
            acc[g].x += p * v.x;
            acc[g].y += p * v.y;
        }
    }
    __syncthreads();

    float2 (*psh)[G_][64] = (float2(*)[G_][64])sbuf;
    #pragma unroll
    for (int g = 0; g < G_; g++) psh[q][g][d2] = acc[g];
    __syncthreads();

    if (q == 0) {
        const size_t obase = ((((size_t)chunk * B_ + b) * NKV_ + h) * G_) * D_;
        #pragma unroll
        for (int g = 0; g < G_; g++) {
            float2 r0 = psh[0][g][d2], r1 = psh[1][g][d2];
            float2 r2 = psh[2][g][d2], r3 = psh[3][g][d2];
            float2 r = make_float2(r0.x + r1.x + r2.x + r3.x,
                                   r0.y + r1.y + r2.y + r3.y);
            *(float2*)&g_opart[obase + g * D_ + d2 * 2] = r;
        }
        if (d2 < G_) {
            size_t msb = ((((size_t)chunk * B_ + b) * NKV_ + h) * G_ + d2) * 2;
            g_ms[msb] = gm[d2];
            g_ms[msb + 1] = gs[d2];
        }
    }
}

// ============================================================
// Combine chunk partials: grid (NH=32, b=32), 128 threads.
// ============================================================
__global__ void attn_combine_kernel() {
    const int head = blockIdx.x;
    const int b = blockIdx.y;
    const int h = head >> 2, g = head & 3;
    const int d = threadIdx.x;

    float M = -1e30f;
    float mloc[NCHUNK];
    #pragma unroll
    for (int c = 0; c < NCHUNK; c++) {
        size_t msb = ((((size_t)c * B_ + b) * NKV_ + h) * G_ + g) * 2;
        mloc[c] = g_ms[msb];
        M = fmaxf(M, mloc[c]);
    }
    float S = 0.f, o = 0.f;
    #pragma unroll
    for (int c = 0; c < NCHUNK; c++) {
        size_t msb = ((((size_t)c * B_ + b) * NKV_ + h) * G_ + g) * 2;
        float w = __expf(mloc[c] - M);
        S += g_ms[msb + 1] * w;
        o += g_opart[(((((size_t)c * B_ + b) * NKV_ + h) * G_ + g)) * D_ + d] * w;
    }
    g_o[b * (NH_ * D_) + head * D_ + d] = o / S;
}

// ============================================================
extern "C" void kernel_launch(void* const* d_in, const int* in_sizes, int n_in,
                              void* d_out, int out_size) {
    const int*   position_ids  = (const int*)  d_in[0];
    const float* hidden_states = (const float*)d_in[1];
    float*       k_buffer      = (float*)      d_in[2];
    float*       v_buffer      = (float*)      d_in[3];
    const int*   out_cache_loc = (const int*)  d_in[4];
    const float* wqkv          = (const float*)d_in[5];
    const float* wo            = (const float*)d_in[6];
    const float* q_norm_w      = (const float*)d_in[7];
    const float* k_norm_w      = (const float*)d_in[8];
    float* out = (float*)d_out;

    float* part_ptr; cudaGetSymbolAddress((void**)&part_ptr, g_part);
    float* o_ptr;    cudaGetSymbolAddress((void**)&o_ptr, g_o);

    // 1. QKV projection (tf32 tensor cores, split-K partials)
    gemm_tf32<<<dim3(QKVN / 64, SPLITK), 256>>>(hidden_states, wqkv, part_ptr, QKVN, H_);
    // 2. reduce + RMSNorm + RoPE + scatter
    norm_rope_scatter<<<dim3(NH_ + 2 * NKV_, B_), 128>>>(
        q_norm_w, k_norm_w, position_ids, out_cache_loc, k_buffer, v_buffer);
    // 3. fused flash-decode (split-KV)
    attn_chunk_kernel<<<dim3(NCHUNK, NKV_, B_), 256>>>(k_buffer, v_buffer);
    // 4. combine partials
    attn_combine_kernel<<<dim3(NH_, B_), 128>>>();
    // 5. O projection (tf32) + reduce
    gemm_tf32<<<dim3(H_ / 64, SPLITK), 256>>>(o_ptr, wo, part_ptr, H_, H_);
    reduce_out<<<(B_ * H_ / 4 + 255) / 256, 256>>>(out, B_ * H_ / 4);
}